// round 10
// baseline (speedup 1.0000x reference)
#include <cuda_runtime.h>

// Problem constants (fixed by the reference setup)
#define DE   200          // entity / output dim
#define DR   200          // relation dim
#define DIN  400          // DE + DR
#define NB   4            // num bases
#define KTOT (NB * DIN)   // 1600 rows of the collapsed matvec

#define NBLK 148          // one wave
#define NTHR 512
#define NMM  37           // consumer (matvec) blocks: blockIdx 0..36
#define KCH  44           // k-rows per consumer block (37*44 = 1628 >= 1600)
#define KPG  22           // max k-rows per thread-group (2 groups x 256 thr)
#define MAXM 1024         // slot capacity (expected ~8 matches)
#define NSPEC 16          // slots processed speculatively (one per warp)

// persistent scratch (static device globals — no allocation).
// g_arrive: low16 = block arrivals, high16 = match count / slot allocator.
//           Reset to 0 by the releaser every launch.
// g_rel:    low32 = monotonically increasing launch sequence, high32 = count.
// g_slot:   bits[48:64) = launch seq tag (stale slots auto-invalid),
//           bits[18:35) = nid, [9:18) = ri, [0:9) = ty.
__device__ unsigned           g_arrive;
__device__ unsigned long long g_rel;
__device__ unsigned long long g_slot[MAXM];

__global__ void __launch_bounds__(NTHR, 1)
fused_kernel(const float* __restrict__ ent,
             const float* __restrict__ relemb,
             const float* __restrict__ basis,
             const float* __restrict__ att,
             const int*   __restrict__ node_id,
             const int*   __restrict__ edge_src,
             const int*   __restrict__ edge_dst,
             const int*   __restrict__ edge_type,
             const int*   __restrict__ rel_index,
             const int*   __restrict__ u_ptr,
             float* __restrict__ out,
             int E) {
    const int tid   = threadIdx.x;
    const bool is_mv = (blockIdx.x < NMM);

    __shared__ float sy[KCH];
    __shared__ float s1[256];
    __shared__ int   s_cnt;

    // Launch sequence: plain (L1-cached) load — one L2 touch per SM.
    // Stable until this launch's own release.
    const unsigned long long rel0 = g_rel;
    const unsigned seq_old = (unsigned)rel0;
    const unsigned seq16   = (seq_old + 1u) & 0xFFFFu;

    // block 0 zeroes the REDG target pre-barrier
    if (blockIdx.x == 0 && tid < DE) out[tid] = 0.0f;

    // consumer blocks prefetch their basis chunk (overlaps the scan)
    const int k0   = blockIdx.x * KCH;
    const int kmax = is_mv ? ((KTOT - k0) < KCH ? (KTOT - k0) : KCH) : 0;
    const int g    = tid >> 8;       // 0 or 1
    const int o    = tid & 255;      // output index within group
    float breg[KPG];
    if (is_mv && o < DE) {
        #pragma unroll
        for (int j = 0; j < KPG; j++) {
            int kk = g * KPG + j;
            breg[j] = (kk < kmax) ? __ldcg(&basis[(size_t)(k0 + kk) * DE + o]) : 0.0f;
        }
    }
    if (tid < KCH) sy[tid] = 0.0f;
    __syncthreads();                 // sy visible before speculative adds

    // ── Phase 1: scan edge_dst (all 148 blocks). A finder allocates its slot
    //    from the SAME atomic counter the barrier uses (high16), resolves the
    //    pointer chain, and publishes ONE seq-tagged 64-bit word. ──
    auto found = [&](int e) {
        unsigned old = atomicAdd(&g_arrive, 1u << 16);
        unsigned p = old >> 16;
        if (p < MAXM) {
            int s  = __ldcg(&edge_src[e]);   // these three issue in parallel
            int ri = __ldcg(&rel_index[e]);
            int ty = __ldcg(&edge_type[e]);
            int nid = __ldcg(&node_id[s]);   // the only serial dependency
            *(volatile unsigned long long*)&g_slot[p] =
                  ((unsigned long long)seq16 << 48)
                | ((unsigned long long)(unsigned)nid << 18)
                | ((unsigned long long)(unsigned)ri  << 9)
                |  (unsigned long long)(unsigned)ty;
        }
    };
    {
        const int u  = *u_ptr;               // L1-cached broadcast
        const int gt = blockIdx.x * NTHR + tid;
        const int GT = NBLK * NTHR;
        const int nv = E >> 2;
        const int4* ed4 = (const int4*)edge_dst;
        for (int i = gt; i < nv; i += 2 * GT) {       // 2-wide MLP
            int  i2 = i + GT;
            bool h2 = i2 < nv;
            int4 v1 = __ldcg(&ed4[i]);
            int4 v2;
            if (h2) v2 = __ldcg(&ed4[i2]);
            int b1 = i << 2;
            if (v1.x == u) found(b1 + 0);
            if (v1.y == u) found(b1 + 1);
            if (v1.z == u) found(b1 + 2);
            if (v1.w == u) found(b1 + 3);
            if (h2) {
                int b2 = i2 << 2;
                if (v2.x == u) found(b2 + 0);
                if (v2.y == u) found(b2 + 1);
                if (v2.z == u) found(b2 + 2);
                if (v2.w == u) found(b2 + 3);
            }
        }
        for (int e = (nv << 2) + gt; e < E; e += GT) {  // scalar tail
            if (__ldcg(&edge_dst[e]) == u) found(e);
        }
    }

    // ── Barrier arrival. The releaser's OWN atomic return carries the final
    //    count (all finds precede all arrivals) — no extra count load. ──
    __syncthreads();
    if (tid == 0) {
        __threadfence();
        unsigned old = atomicAdd(&g_arrive, 1u);
        if ((old & 0xFFFFu) == NBLK - 1) {           // releaser
            unsigned cnt = old >> 16;
            g_arrive = 0;                             // reset for next launch
            __threadfence();
            atomicExch(&g_rel, ((unsigned long long)cnt << 32)
                               | (unsigned long long)(seq_old + 1u));
        }
    }

    if (!is_mv) return;                               // scan-only blocks done

    // ── Speculative consume (pre-release): warp w owns slot w. Poll the
    //    seq tag; process the instant it is published. Fall out when the
    //    release says this slot will never fill. ──
    {
        const int wid  = tid >> 5;
        const int lane = tid & 31;
        if (wid < NSPEC) {
            const int mm = wid;
            unsigned long long v;
            bool have = false;
            for (;;) {
                v = *(volatile unsigned long long*)&g_slot[mm];
                if ((unsigned)(v >> 48) == seq16) { have = true; break; }
                unsigned long long r = *(volatile unsigned long long*)&g_rel;
                if ((unsigned)r != seq_old) {         // released
                    int cnt = (int)(r >> 32);
                    if (mm >= cnt) break;             // never fills
                    __threadfence();                  // acquire
                    v = *(volatile unsigned long long*)&g_slot[mm];
                    have = ((unsigned)(v >> 48) == seq16);
                    break;
                }
            }
            if (have) {
                int nid = (int)((v >> 18) & 0x1FFFF);
                int ri  = (int)((v >> 9) & 0x1FF);
                int ty  = (int)(v & 0x1FF);
                #pragma unroll
                for (int h = 0; h < 2; h++) {
                    int kk = lane + h * 32;
                    if (kk < kmax) {
                        int k = k0 + kk;
                        int b = k / DIN;
                        int i = k - b * DIN;
                        float x = (i < DE)
                            ? __ldcg(&ent[(size_t)nid * DE + i])
                            : __ldcg(&relemb[(size_t)ri * DR + (i - DE)]);
                        float a = att[ty * NB + b];
                        atomicAdd(&sy[kk], a * x);
                    }
                }
            }
        }
    }

    // ── Release wait (usually already satisfied) + rare tail for cnt>16 ──
    if (tid == 0) {
        unsigned long long r;
        do { r = *(volatile unsigned long long*)&g_rel; }
        while ((unsigned)r == seq_old);
        __threadfence();                              // acquire
        s_cnt = (int)(r >> 32);
    }
    __syncthreads();
    const int   cnt  = s_cnt;
    const int   cntc = cnt < MAXM ? cnt : MAXM;
    const float inv  = 1.0f / fmaxf((float)cnt, 1.0f);

    if (cntc > NSPEC) {                               // rare (expected cnt≈8)
        const int total = (cntc - NSPEC) * kmax;
        for (int p = tid; p < total; p += NTHR) {
            int mm = NSPEC + p / kmax;
            int kk = p - (mm - NSPEC) * kmax;
            unsigned long long v = g_slot[mm];
            int nid = (int)((v >> 18) & 0x1FFFF);
            int ri  = (int)((v >> 9) & 0x1FF);
            int ty  = (int)(v & 0x1FF);
            int k = k0 + kk;
            int b = k / DIN;
            int i = k - b * DIN;
            float x = (i < DE)
                ? __ldcg(&ent[(size_t)nid * DE + i])
                : __ldcg(&relemb[(size_t)ri * DR + (i - DE)]);
            float a = att[ty * NB + b];
            atomicAdd(&sy[kk], a * x);
        }
        __syncthreads();
    }
    __syncthreads();                                  // sy complete

    // combine halves in smem -> ONE REDG lane per output element, pre-scaled
    float acc = 0.0f;
    if (o < DE) {
        #pragma unroll
        for (int j = 0; j < KPG; j++) {
            int kk = g * KPG + j;
            if (kk < kmax) acc += sy[kk] * breg[j];
        }
        if (g == 1) s1[o] = acc;
    }
    __syncthreads();
    if (o < DE && g == 0 && cntc > 0) {
        atomicAdd(&out[o], (acc + s1[o]) * inv);      // fire-and-forget REDG
    }
    // no reset tail: g_arrive reset by releaser, g_rel monotonic,
    // slots invalidated by seq tag.
}

extern "C" void kernel_launch(void* const* d_in, const int* in_sizes, int n_in,
                              void* d_out, int out_size) {
    const float* ent    = (const float*)d_in[0];  // [100000, 200]
    const float* relemb = (const float*)d_in[1];  // [200, 200]
    const float* basis  = (const float*)d_in[2];  // [4, 400, 200]
    const float* att    = (const float*)d_in[3];  // [400, 4]
    const int* node_id  = (const int*)d_in[4];    // [50000]
    const int* edge_src = (const int*)d_in[5];    // [400000]
    const int* edge_dst = (const int*)d_in[6];    // [400000]
    const int* edge_typ = (const int*)d_in[7];    // [400000]
    const int* rel_idx  = (const int*)d_in[8];    // [400000]
    const int* u_ptr    = (const int*)d_in[9];    // scalar
    float* out = (float*)d_out;                   // [200]

    int E = in_sizes[6];

    fused_kernel<<<NBLK, NTHR>>>(ent, relemb, basis, att,
                                 node_id, edge_src, edge_dst, edge_typ, rel_idx,
                                 u_ptr, out, E);
}